// round 15
// baseline (speedup 1.0000x reference)
#include <cuda_runtime.h>
#include <cuda_fp16.h>
#include <cstdint>
#include <cstddef>

#define T_   512
#define B_   128
#define H_   512
#define G4   2048
#define NG   16      // CTAs per cluster (phase 2)

// ---------------- scratch (device globals; no allocation) ----------------
__device__ __half   g_Xg[(size_t)T_ * B_ * G4];     // 256 MB fp16: x@W_ih^T + bias
__device__ __half   g_lat16[(size_t)T_ * B_ * 512]; // 64 MB, tiled [tt][kt][r][32]
__device__ uint32_t g_w16p[16 * 16 * 2 * 128 * 8];  // 2 MB, smem-layout-ready
__device__ __half   g_h2[2][B_ * H_];               // double-buffered fp16 h

// ---------------- helpers ----------------
__device__ __forceinline__ void mma_f16(float c[4], const uint32_t a[4],
                                        uint32_t b0, uint32_t b1) {
    asm volatile(
        "mma.sync.aligned.m16n8k16.row.col.f32.f16.f16.f32 "
        "{%0,%1,%2,%3},{%4,%5,%6,%7},{%8,%9},{%0,%1,%2,%3};"
        : "+f"(c[0]), "+f"(c[1]), "+f"(c[2]), "+f"(c[3])
        : "r"(a[0]), "r"(a[1]), "r"(a[2]), "r"(a[3]), "r"(b0), "r"(b1));
}
__device__ __forceinline__ void ldsm4(uint32_t r[4], uint32_t saddr) {
    asm volatile("ldmatrix.sync.aligned.m8n8.x4.shared.b16 {%0,%1,%2,%3},[%4];"
        : "=r"(r[0]), "=r"(r[1]), "=r"(r[2]), "=r"(r[3]) : "r"(saddr));
}
__device__ __forceinline__ void cp16(uint32_t sdst, const void* gsrc) {
    asm volatile("cp.async.ca.shared.global [%0],[%1],16;" :: "r"(sdst), "l"(gsrc));
}
__device__ __forceinline__ uint32_t h2u(float x, float y) {
    __half2 h = __floats2half2_rn(x, y);
    return *reinterpret_cast<uint32_t*>(&h);
}
__device__ __forceinline__ int pidx(int p) { return (p & 3) * 2 + (p >> 2); }
__device__ __forceinline__ float sigf(float x) {
    return __fdividef(1.0f, 1.0f + __expf(-x));
}
__device__ __forceinline__ float tanhfast(float x) {
    return 1.0f - 2.0f * __fdividef(1.0f, __expf(2.0f * x) + 1.0f);
}
__device__ __forceinline__ uint32_t ctarank() {
    uint32_t r; asm("mov.u32 %0, %%cluster_ctarank;" : "=r"(r)); return r;
}
__device__ __forceinline__ uint32_t mapa_u32(uint32_t addr, uint32_t rank) {
    uint32_t r; asm("mapa.shared::cluster.u32 %0, %1, %2;" : "=r"(r) : "r"(addr), "r"(rank));
    return r;
}

// ==========================================================================
// Convert latent -> fp16, tiled layout [(tt*16+kt)*128 + r][32]   (R12)
// ==========================================================================
__global__ void __launch_bounds__(256) conv_lat(const float* __restrict__ latent) {
    const size_t n = (size_t)T_ * B_ * 512 / 2;
    uint32_t* dst = reinterpret_cast<uint32_t*>(g_lat16);
    for (size_t i = (size_t)blockIdx.x * 256 + threadIdx.x; i < n;
         i += (size_t)gridDim.x * 256) {
        size_t hidx = i * 2;
        int    k    = (int)(hidx & 31);
        size_t rest = hidx >> 5;
        int    r    = (int)(rest & 127);
        size_t r2   = rest >> 7;
        int    kt   = (int)(r2 & 15);
        size_t tt   = r2 >> 4;
        size_t src  = (tt * 128 + r) * 512 + kt * 32 + k;
        float2 v = *reinterpret_cast<const float2*>(&latent[src]);
        dst[i] = h2u(v.x, v.y);
    }
}

// ==========================================================================
// Convert w_ih -> fp16 permuted smem layout (R12)
// ==========================================================================
__global__ void __launch_bounds__(256) conv_w(const float* __restrict__ w_ih) {
    const int total = 16 * 16 * 2 * 128 * 8;
    for (int d = blockIdx.x * 256 + threadIdx.x; d < total; d += gridDim.x * 256) {
        int q  = d & 7, r = (d >> 3) & 127, ks = (d >> 10) & 1;
        int kt = (d >> 11) & 15, nt = d >> 15;
        int p  = (q & 1) ? (4 + (q >> 1)) : (q >> 1);
        int k  = kt * 32 + ks * 16 + p * 2;
        int n  = nt * 128 + r;
        float2 v = *reinterpret_cast<const float2*>(&w_ih[(size_t)n * 512 + k]);
        g_w16p[d] = h2u(v.x, v.y);
    }
}

// ==========================================================================
// Phase 1: Xg = latent @ W_ih^T + bias -> fp16. 4-stage cp.async ring (R12).
// ==========================================================================
__global__ void __launch_bounds__(256, 2) xgemm_fp16(
    const float* __restrict__ b_ih, const float* __restrict__ b_hh)
{
    extern __shared__ __align__(16) unsigned char sm[];
    float* bias_s = (float*)sm;

    const int tid  = threadIdx.x;
    const int nt   = blockIdx.x & 15;
    const int tt   = blockIdx.x >> 4;
    const int n0   = nt * 128;
    const int lane = tid & 31, w = tid >> 5;
    const int mb   = (w & 3) * 32;
    const int nb2  = (w >> 2) * 64;

    if (tid < 128) bias_s[tid] = b_ih[n0 + tid] + b_hh[n0 + tid];

    const uint32_t smBase = (uint32_t)__cvta_generic_to_shared(sm);

    float c[2][8][4];
    #pragma unroll
    for (int i = 0; i < 2; i++)
        #pragma unroll
        for (int jx = 0; jx < 8; jx++)
            #pragma unroll
            for (int k = 0; k < 4; k++) c[i][jx][k] = 0.f;

    auto ISSUE = [&](int kt, int s) {
        uint32_t Aa = smBase + 512 + s * 18432;
        uint32_t Ba = Aa + 10240;
        const __half* asrc = g_lat16 + ((size_t)(tt * 16 + kt) << 12);
        #pragma unroll
        for (int i = 0; i < 2; i++) {
            int cch = tid + i * 256;
            int r = cch >> 2, c4 = cch & 3;
            cp16(Aa + r * 80 + c4 * 16, asrc + r * 32 + c4 * 8);
        }
        const uint32_t* wsrc = g_w16p + (size_t)(nt * 16 + kt) * 2048;
        #pragma unroll
        for (int i = 0; i < 2; i++) {
            int cch = tid + i * 256;
            cp16(Ba + cch * 16, wsrc + cch * 4);
        }
        asm volatile("cp.async.commit_group;");
    };

    auto COMPUTE = [&](int s) {
        const uint32_t* Au = (const uint32_t*)(sm + 512 + s * 18432);
        const uint32_t* Bs = (const uint32_t*)(sm + 512 + s * 18432 + 10240);
        #pragma unroll
        for (int ks = 0; ks < 2; ++ks) {
            uint32_t a[2][4];
            #pragma unroll
            for (int mi = 0; mi < 2; mi++) {
                int base = (mb + mi * 16 + (lane >> 2)) * 20 + ks * 8 + (lane & 3);
                a[mi][0] = Au[base];       a[mi][1] = Au[base + 160];
                a[mi][2] = Au[base + 4];   a[mi][3] = Au[base + 164];
            }
            #pragma unroll
            for (int ni = 0; ni < 8; ++ni) {
                int n = nb2 + ni * 8 + (lane >> 2);
                uint2 bv = *reinterpret_cast<const uint2*>(&Bs[(ks * 128 + n) * 8 + (lane & 3) * 2]);
                mma_f16(c[0][ni], a[0], bv.x, bv.y);
                mma_f16(c[1][ni], a[1], bv.x, bv.y);
            }
        }
    };

    ISSUE(0, 0); ISSUE(1, 1); ISSUE(2, 2);
    #pragma unroll 1
    for (int kt = 0; kt < 16; ++kt) {
        if (kt <= 13)      asm volatile("cp.async.wait_group 2;");
        else if (kt == 14) asm volatile("cp.async.wait_group 1;");
        else               asm volatile("cp.async.wait_group 0;");
        __syncthreads();
        COMPUTE(kt & 3);
        if (kt + 3 < 16) ISSUE(kt + 3, (kt + 3) & 3);
    }

    #pragma unroll
    for (int mi = 0; mi < 2; mi++) {
        #pragma unroll
        for (int ni = 0; ni < 8; ni++) {
            int r    = mb + mi * 16 + (lane >> 2);
            int colL = nb2 + ni * 8 + (lane & 3) * 2;
            float bv0 = bias_s[colL], bv1 = bias_s[colL + 1];
            size_t base = ((size_t)(tt * 128 + r)) * G4 + n0 + colL;
            *reinterpret_cast<uint32_t*>(&g_Xg[base]) =
                h2u(c[mi][ni][0] + bv0, c[mi][ni][1] + bv1);
            *reinterpret_cast<uint32_t*>(&g_Xg[base + (size_t)8 * G4]) =
                h2u(c[mi][ni][2] + bv0, c[mi][ni][3] + bv1);
        }
    }
}

// ==========================================================================
// Phase 2: persistent recurrence — R12 compute structure, but inter-CTA sync
// via cluster-remote mbarrier arrivals (signal over DSMEM, data over L2).
// 8 clusters x 16 CTAs. Producer: h STGs -> __syncthreads -> warp0 lanes<16
// remote-arrive each peer's mbar[(t+1)&1]. Consumer: try_wait parity on its
// LOCAL mbar (HW sleep). Double-buffered barriers, count=16, ph=(t>>1)&1.
// smem: W init region [0,196608) | A_s @196608 (16640) | mbars @213248 (16B)
// ==========================================================================
__global__ void __launch_bounds__(256, 1) lstm_rec16(
    const float*    __restrict__ h0,
    const float*    __restrict__ c0,
    const uint32_t* __restrict__ reset,    // [B,T]
    const uint32_t* __restrict__ clearm,   // [B,T]
    const float*    __restrict__ nstd,     // [B,T]
    const float*    __restrict__ noise,    // [T,B,H]
    const float*    __restrict__ w_hh,     // [2048,512]
    float*          __restrict__ out)
{
    extern __shared__ __align__(16) unsigned char sm[];
    __half* W_s = (__half*)sm;                       // 196608 B (init only)

    const int tid  = threadIdx.x;
    const int lane = tid & 31, w = tid >> 5;
    const int cg   = (int)ctarank();
    const int mg   = blockIdx.x >> 4;
    const int b0   = mg * 16, j0 = cg * 32;

    const uint32_t smBase = (uint32_t)__cvta_generic_to_shared(sm);
    const uint32_t As_sa  = smBase + 196608;
    const uint32_t mb0    = smBase + 213248;         // mbar[0] @213248, mbar[1] @213256

    // ---- W_s fill (once), GATE-INTERLEAVED col order (R12)
    for (int e = tid; e < 4096; e += 256) {
        int ks = e >> 7, c = e & 127;
        int wp = c >> 4, idx = c & 15;
        int ti = idx >> 3, p = idx & 7;
        int n  = (ti * 2 + (p & 1)) * 512 + j0 + wp * 4 + (p >> 1);
        const float4* wpn = reinterpret_cast<const float4*>(&w_hh[(size_t)n * 512 + ks * 16]);
        float4 w0 = wpn[0], w1 = wpn[1], w2 = wpn[2], w3 = wpn[3];
        uint4 lo, hi;
        lo.x = h2u(w0.x, w0.y); lo.y = h2u(w0.z, w0.w);
        lo.z = h2u(w1.x, w1.y); lo.w = h2u(w1.z, w1.w);
        hi.x = h2u(w2.x, w2.y); hi.y = h2u(w2.z, w2.w);
        hi.z = h2u(w3.x, w3.y); hi.w = h2u(w3.z, w3.w);
        char* base = (char*)W_s + (size_t)(ks * 128 + c) * 48;
        *reinterpret_cast<uint4*>(base)      = lo;
        *reinterpret_cast<uint4*>(base + 16) = hi;
    }
    __syncthreads();

    // ---- load all W fragments into registers
    const int mq = lane >> 3, rl = lane & 7;
    const int rowL = (mq & 1) * 8 + rl;
    const int koff = (mq >> 1) * 8;
    const uint32_t aAddr0 = As_sa + rowL * 1040 + koff * 2;
    const uint32_t bAddr0 = smBase + (w * 16 + rowL) * 48 + koff * 2;
    uint32_t bb[32][4];
    #pragma unroll
    for (int ks = 0; ks < 32; ++ks)
        ldsm4(bb[ks], bAddr0 + ks * 6144);

    // ---- mbarrier init (count = 16 arrivals per phase) + cluster sync
    if (tid == 0) {
        asm volatile("mbarrier.init.shared.b64 [%0], %1;" :: "r"(mb0),     "r"(16u) : "memory");
        asm volatile("mbarrier.init.shared.b64 [%0], %1;" :: "r"(mb0 + 8), "r"(16u) : "memory");
    }
    __syncthreads();
    asm volatile("barrier.cluster.arrive.aligned;" ::: "memory");
    asm volatile("barrier.cluster.wait.aligned;" ::: "memory");

    // ---- epilogue lane mapping (R12: gates land in-lane)
    const int rE = lane >> 2, jE = lane & 3;
    const int bA = b0 + rE, bB = bA + 8;
    const int j  = j0 + w * 4 + jE;

    // ---- init h/c with step-0 preprocessing; publish via remote arrives
    float cst0, cst1;
    {
        float hA = h0[bA * H_ + j], cA = c0[bA * H_ + j];
        float hB = h0[bB * H_ + j], cB = c0[bB * H_ + j];
        bool mA = ((reset[bA * T_] | clearm[bA * T_]) != 0u);
        bool mB = ((reset[bB * T_] | clearm[bB * T_]) != 0u);
        if (mA) { hA = cA = 0.f; }
        if (mB) { hB = cB = 0.f; }
        float nzA = noise[(size_t)bA * H_ + j] * nstd[bA * T_];
        float nzB = noise[(size_t)bB * H_ + j] * nstd[bB * T_];
        hA += nzA; cA += nzA;
        hB += nzB; cB += nzB;
        g_h2[0][bA * H_ + j] = __float2half_rn(hA);
        g_h2[0][bB * H_ + j] = __float2half_rn(hB);
        cst0 = cA; cst1 = cB;
    }
    __syncthreads();
    if (w == 0 && lane < NG) {
        uint32_t rm = mapa_u32(mb0, (uint32_t)lane);
        asm volatile("mbarrier.arrive.shared::cluster.b64 _, [%0];" :: "r"(rm) : "memory");
    }

    const int stR = tid >> 6;
    const int stC = tid & 63;

    for (int t = 0; t < T_; ++t) {
        // ---- prefetch (independent of h[t]) ----
        size_t xbA = ((size_t)t * B_ + bA) * G4 + j;
        size_t xbB = ((size_t)t * B_ + bB) * G4 + j;
        float xI0 = __half2float(g_Xg[xbA]),        xI1 = __half2float(g_Xg[xbB]);
        float xF0 = __half2float(g_Xg[xbA + 512]),  xF1 = __half2float(g_Xg[xbB + 512]);
        float xG0 = __half2float(g_Xg[xbA + 1024]), xG1 = __half2float(g_Xg[xbB + 1024]);
        float xO0 = __half2float(g_Xg[xbA + 1536]), xO1 = __half2float(g_Xg[xbB + 1536]);
        unsigned mN0 = 0, mN1 = 0;
        float sN0 = 0.f, sN1 = 0.f, nz0 = 0.f, nz1 = 0.f;
        if (t + 1 < T_) {
            mN0 = reset[bA * T_ + t + 1] | clearm[bA * T_ + t + 1];
            mN1 = reset[bB * T_ + t + 1] | clearm[bB * T_ + t + 1];
            sN0 = nstd[bA * T_ + t + 1];
            sN1 = nstd[bB * T_ + t + 1];
            nz0 = noise[((size_t)(t + 1) * B_ + bA) * H_ + j];
            nz1 = noise[((size_t)(t + 1) * B_ + bB) * H_ + j];
        }

        // ---- wait for all 16 producers of h[t] (local mbar, HW sleep) ----
        {
            uint32_t mb = mb0 + (t & 1) * 8;
            uint32_t ph = (t >> 1) & 1;
            asm volatile(
                "{\n\t.reg .pred P;\n"
                "WAITL_%=:\n\t"
                "mbarrier.try_wait.parity.acquire.cluster.shared::cta.b64 P, [%0], %1, 0x989680;\n\t"
                "@!P bra WAITL_%=;\n\t}"
                :: "r"(mb), "r"(ph) : "memory");
        }

        // ---- stage h tile [16][512] fp16 via cp.async ----
        const __half* __restrict__ hsrc = g_h2[t & 1];
        #pragma unroll
        for (int i = 0; i < 4; i++) {
            int r = stR + i * 4;
            cp16(As_sa + r * 1040 + stC * 16, &hsrc[(b0 + r) * H_ + stC * 8]);
        }
        asm volatile("cp.async.commit_group;");
        asm volatile("cp.async.wait_group 0;");
        __syncthreads();

        // ---- GEMM: 32 ksteps, 4 accumulation chains (R12) ----
        float a0A[4] = {0.f, 0.f, 0.f, 0.f}, a1A[4] = {0.f, 0.f, 0.f, 0.f};
        float a0B[4] = {0.f, 0.f, 0.f, 0.f}, a1B[4] = {0.f, 0.f, 0.f, 0.f};
        #pragma unroll
        for (int ks = 0; ks < 32; ks += 2) {
            uint32_t a[4], a2[4];
            ldsm4(a,  aAddr0 + ks * 32);
            ldsm4(a2, aAddr0 + ks * 32 + 32);
            mma_f16(a0A, a,  bb[ks][0],     bb[ks][2]);
            mma_f16(a1A, a,  bb[ks][1],     bb[ks][3]);
            mma_f16(a0B, a2, bb[ks + 1][0], bb[ks + 1][2]);
            mma_f16(a1B, a2, bb[ks + 1][1], bb[ks + 1][3]);
        }
        float gi0 = a0A[0] + a0B[0], gf0 = a0A[1] + a0B[1];
        float gi1 = a0A[2] + a0B[2], gf1 = a0A[3] + a0B[3];
        float gg0 = a1A[0] + a1B[0], go0 = a1A[1] + a1B[1];
        float gg1 = a1A[2] + a1B[2], go1 = a1A[3] + a1B[3];

        // ---- gates + state update + next-step preprocessing ----
        float iA = sigf(gi0 + xI0),     iB = sigf(gi1 + xI1);
        float fA = sigf(gf0 + xF0),     fB = sigf(gf1 + xF1);
        float gA = tanhfast(gg0 + xG0), gB = tanhfast(gg1 + xG1);
        float oA = sigf(go0 + xO0),     oB = sigf(go1 + xO1);

        float cnA = fA * cst0 + iA * gA;
        float cnB = fB * cst1 + iB * gB;
        float hnA = oA * tanhfast(cnA);
        float hnB = oB * tanhfast(cnB);

        if (t + 1 < T_) {
            float hwA = mN0 ? 0.f : hnA, cwA = mN0 ? 0.f : cnA;
            float hwB = mN1 ? 0.f : hnB, cwB = mN1 ? 0.f : cnB;
            hwA += nz0 * sN0; cwA += nz0 * sN0;
            hwB += nz1 * sN1; cwB += nz1 * sN1;
            g_h2[(t + 1) & 1][bA * H_ + j] = __float2half_rn(hwA);
            g_h2[(t + 1) & 1][bB * H_ + j] = __float2half_rn(hwB);
            cst0 = cwA; cst1 = cwB;
        }

        __syncthreads();
        if (t + 1 < T_ && w == 0 && lane < NG) {
            uint32_t rm = mapa_u32(mb0 + ((t + 1) & 1) * 8, (uint32_t)lane);
            asm volatile("mbarrier.arrive.shared::cluster.b64 _, [%0];" :: "r"(rm) : "memory");
        }

        // ---- off-critical-path output stores ----
        out[((size_t)t * B_ + bA) * H_ + j] = hnA;
        out[((size_t)t * B_ + bB) * H_ + j] = hnB;
        if (t == T_ - 1) {
            out[(size_t)T_ * (B_ * H_)           + bA * H_ + j] = hnA;
            out[(size_t)T_ * (B_ * H_)           + bB * H_ + j] = hnB;
            out[(size_t)T_ * (B_ * H_) + B_ * H_ + bA * H_ + j] = cnA;
            out[(size_t)T_ * (B_ * H_) + B_ * H_ + bB * H_ + j] = cnB;
        }
    }

    // ---- all arrivals consumed; exit together (remote-smem lifetime) ----
    asm volatile("barrier.cluster.arrive.aligned;" ::: "memory");
    asm volatile("barrier.cluster.wait.aligned;" ::: "memory");
}

// ==========================================================================
extern "C" void kernel_launch(void* const* d_in, const int* in_sizes, int n_in,
                              void* d_out, int out_size) {
    (void)in_sizes; (void)n_in; (void)out_size;
    const float*    latent = (const float*)d_in[0];
    const float*    h0     = (const float*)d_in[1];
    const float*    c0     = (const float*)d_in[2];
    const uint32_t* reset  = (const uint32_t*)d_in[3];
    const uint32_t* clearm = (const uint32_t*)d_in[4];
    const float*    nstd   = (const float*)d_in[5];
    const float*    noise  = (const float*)d_in[6];
    const float*    w_ih   = (const float*)d_in[7];
    const float*    w_hh   = (const float*)d_in[8];
    const float*    b_ih   = (const float*)d_in[9];
    const float*    b_hh   = (const float*)d_in[10];
    float* out = (float*)d_out;

    const int smem1 = 512 + 4 * 18432;                 // 74240 B
    const int smem2 = 213264;                          // W region + A_s + 2 mbars
    cudaFuncSetAttribute(xgemm_fp16, cudaFuncAttributeMaxDynamicSharedMemorySize, smem1);
    cudaFuncSetAttribute(lstm_rec16, cudaFuncAttributeMaxDynamicSharedMemorySize, smem2);
    cudaFuncSetAttribute(lstm_rec16, cudaFuncAttributeNonPortableClusterSizeAllowed, 1);

    conv_lat<<<4096, 256>>>(latent);
    conv_w<<<512, 256>>>(w_ih);
    xgemm_fp16<<<512 * 16, 256, smem1>>>(b_ih, b_hh);

    cudaLaunchConfig_t cfg = {};
    cfg.gridDim  = dim3(128, 1, 1);
    cfg.blockDim = dim3(256, 1, 1);
    cfg.dynamicSmemBytes = smem2;
    cudaLaunchAttribute attrs[1];
    attrs[0].id = cudaLaunchAttributeClusterDimension;
    attrs[0].val.clusterDim.x = NG;
    attrs[0].val.clusterDim.y = 1;
    attrs[0].val.clusterDim.z = 1;
    cfg.attrs = attrs;
    cfg.numAttrs = 1;
    cudaLaunchKernelEx(&cfg, lstm_rec16,
                       h0, c0, reset, clearm, nstd, noise, w_hh, out);
}

// round 16
// speedup vs baseline: 1.5981x; 1.5981x over previous
#include <cuda_runtime.h>
#include <cuda_fp16.h>
#include <cstdint>
#include <cstddef>

#define T_   512
#define B_   128
#define H_   512
#define G4   2048
#define NG   16      // CTAs per row-group (phase 2)

// ---------------- scratch (device globals; no allocation) ----------------
__device__ __half   g_Xg[(size_t)T_ * B_ * G4];     // 256 MB fp16: x@W_ih^T + bias
__device__ __half   g_lat16[(size_t)T_ * B_ * 512]; // 64 MB, tiled [tt][kt][r][32]
__device__ uint32_t g_w16p[16 * 16 * 2 * 128 * 8];  // 2 MB, smem-layout-ready
__device__ __half   g_h2[2][B_ * H_];               // double-buffered fp16 h
__device__ unsigned g_flag[8][T_ + 1][NG];          // per-group per-step flags

// ---------------- helpers ----------------
__device__ __forceinline__ void mma_f16(float c[4], const uint32_t a[4],
                                        uint32_t b0, uint32_t b1) {
    asm volatile(
        "mma.sync.aligned.m16n8k16.row.col.f32.f16.f16.f32 "
        "{%0,%1,%2,%3},{%4,%5,%6,%7},{%8,%9},{%0,%1,%2,%3};"
        : "+f"(c[0]), "+f"(c[1]), "+f"(c[2]), "+f"(c[3])
        : "r"(a[0]), "r"(a[1]), "r"(a[2]), "r"(a[3]), "r"(b0), "r"(b1));
}
__device__ __forceinline__ void ldsm4(uint32_t r[4], uint32_t saddr) {
    asm volatile("ldmatrix.sync.aligned.m8n8.x4.shared.b16 {%0,%1,%2,%3},[%4];"
        : "=r"(r[0]), "=r"(r[1]), "=r"(r[2]), "=r"(r[3]) : "r"(saddr));
}
__device__ __forceinline__ void cp16(uint32_t sdst, const void* gsrc) {
    asm volatile("cp.async.ca.shared.global [%0],[%1],16;" :: "r"(sdst), "l"(gsrc));
}
__device__ __forceinline__ uint32_t h2u(float x, float y) {
    __half2 h = __floats2half2_rn(x, y);
    return *reinterpret_cast<uint32_t*>(&h);
}
__device__ __forceinline__ float sigf(float x) {
    return __fdividef(1.0f, 1.0f + __expf(-x));
}
__device__ __forceinline__ float tanhfast(float x) {
    return 1.0f - 2.0f * __fdividef(1.0f, __expf(2.0f * x) + 1.0f);
}

// ==========================================================================
// Convert latent -> fp16, tiled layout [(tt*16+kt)*128 + r][32]   (R12)
// ==========================================================================
__global__ void __launch_bounds__(256) conv_lat(const float* __restrict__ latent) {
    const size_t n = (size_t)T_ * B_ * 512 / 2;   // half2 units
    uint32_t* dst = reinterpret_cast<uint32_t*>(g_lat16);
    for (size_t i = (size_t)blockIdx.x * 256 + threadIdx.x; i < n;
         i += (size_t)gridDim.x * 256) {
        size_t hidx = i * 2;
        int    k    = (int)(hidx & 31);
        size_t rest = hidx >> 5;
        int    r    = (int)(rest & 127);
        size_t r2   = rest >> 7;
        int    kt   = (int)(r2 & 15);
        size_t tt   = r2 >> 4;
        size_t src  = (tt * 128 + r) * 512 + kt * 32 + k;
        float2 v = *reinterpret_cast<const float2*>(&latent[src]);
        dst[i] = h2u(v.x, v.y);
    }
}

// ==========================================================================
// Convert w_ih -> fp16 permuted smem layout (R12)
// ==========================================================================
__global__ void __launch_bounds__(256) conv_w(const float* __restrict__ w_ih) {
    const int total = 16 * 16 * 2 * 128 * 8;
    for (int d = blockIdx.x * 256 + threadIdx.x; d < total; d += gridDim.x * 256) {
        int q  = d & 7, r = (d >> 3) & 127, ks = (d >> 10) & 1;
        int kt = (d >> 11) & 15, nt = d >> 15;
        int p  = (q & 1) ? (4 + (q >> 1)) : (q >> 1);
        int k  = kt * 32 + ks * 16 + p * 2;
        int n  = nt * 128 + r;
        float2 v = *reinterpret_cast<const float2*>(&w_ih[(size_t)n * 512 + k]);
        g_w16p[d] = h2u(v.x, v.y);
    }
}

// ==========================================================================
// Phase 1: Xg = latent @ W_ih^T + bias -> fp16. 4-stage cp.async ring (R12).
// ==========================================================================
__global__ void __launch_bounds__(256, 2) xgemm_fp16(
    const float* __restrict__ b_ih, const float* __restrict__ b_hh)
{
    extern __shared__ __align__(16) unsigned char sm[];
    float* bias_s = (float*)sm;

    const int tid  = threadIdx.x;
    const int nt   = blockIdx.x & 15;
    const int tt   = blockIdx.x >> 4;
    const int n0   = nt * 128;
    const int lane = tid & 31, w = tid >> 5;
    const int mb   = (w & 3) * 32;
    const int nb2  = (w >> 2) * 64;

    if (tid < 128) bias_s[tid] = b_ih[n0 + tid] + b_hh[n0 + tid];

    const uint32_t smBase = (uint32_t)__cvta_generic_to_shared(sm);

    float c[2][8][4];
    #pragma unroll
    for (int i = 0; i < 2; i++)
        #pragma unroll
        for (int jx = 0; jx < 8; jx++)
            #pragma unroll
            for (int k = 0; k < 4; k++) c[i][jx][k] = 0.f;

    auto ISSUE = [&](int kt, int s) {
        uint32_t Aa = smBase + 512 + s * 18432;
        uint32_t Ba = Aa + 10240;
        const __half* asrc = g_lat16 + ((size_t)(tt * 16 + kt) << 12);
        #pragma unroll
        for (int i = 0; i < 2; i++) {
            int cch = tid + i * 256;
            int r = cch >> 2, c4 = cch & 3;
            cp16(Aa + r * 80 + c4 * 16, asrc + r * 32 + c4 * 8);
        }
        const uint32_t* wsrc = g_w16p + (size_t)(nt * 16 + kt) * 2048;
        #pragma unroll
        for (int i = 0; i < 2; i++) {
            int cch = tid + i * 256;
            cp16(Ba + cch * 16, wsrc + cch * 4);
        }
        asm volatile("cp.async.commit_group;");
    };

    auto COMPUTE = [&](int s) {
        const uint32_t* Au = (const uint32_t*)(sm + 512 + s * 18432);
        const uint32_t* Bs = (const uint32_t*)(sm + 512 + s * 18432 + 10240);
        #pragma unroll
        for (int ks = 0; ks < 2; ++ks) {
            uint32_t a[2][4];
            #pragma unroll
            for (int mi = 0; mi < 2; mi++) {
                int base = (mb + mi * 16 + (lane >> 2)) * 20 + ks * 8 + (lane & 3);
                a[mi][0] = Au[base];       a[mi][1] = Au[base + 160];
                a[mi][2] = Au[base + 4];   a[mi][3] = Au[base + 164];
            }
            #pragma unroll
            for (int ni = 0; ni < 8; ++ni) {
                int n = nb2 + ni * 8 + (lane >> 2);
                uint2 bv = *reinterpret_cast<const uint2*>(&Bs[(ks * 128 + n) * 8 + (lane & 3) * 2]);
                mma_f16(c[0][ni], a[0], bv.x, bv.y);
                mma_f16(c[1][ni], a[1], bv.x, bv.y);
            }
        }
    };

    ISSUE(0, 0); ISSUE(1, 1); ISSUE(2, 2);
    #pragma unroll 1
    for (int kt = 0; kt < 16; ++kt) {
        if (kt <= 13)      asm volatile("cp.async.wait_group 2;");
        else if (kt == 14) asm volatile("cp.async.wait_group 1;");
        else               asm volatile("cp.async.wait_group 0;");
        __syncthreads();
        COMPUTE(kt & 3);
        if (kt + 3 < 16) ISSUE(kt + 3, (kt + 3) & 3);
    }

    #pragma unroll
    for (int mi = 0; mi < 2; mi++) {
        #pragma unroll
        for (int ni = 0; ni < 8; ni++) {
            int r    = mb + mi * 16 + (lane >> 2);
            int colL = nb2 + ni * 8 + (lane & 3) * 2;
            float bv0 = bias_s[colL], bv1 = bias_s[colL + 1];
            size_t base = ((size_t)(tt * 128 + r)) * G4 + n0 + colL;
            *reinterpret_cast<uint32_t*>(&g_Xg[base]) =
                h2u(c[mi][ni][0] + bv0, c[mi][ni][1] + bv1);
            *reinterpret_cast<uint32_t*>(&g_Xg[base + (size_t)8 * G4]) =
                h2u(c[mi][ni][2] + bv0, c[mi][ni][3] + bv1);
        }
    }
}

// ==========================================================================
// Phase 2: persistent recurrence — R12 structure with TWO-CHUNK h staging:
// stage k-cols [0,256) and [256,512) as separate commit groups; GEMM over
// ks 0..15 overlaps the in-flight second chunk. One extra __syncthreads.
// All else identical to R12 (gate-interleaved W, no-shuffle epilogue,
// per-rank flags + parallel poll, register-resident W fragments).
// ==========================================================================
__global__ void __launch_bounds__(256, 1) lstm_rec16(
    const float*    __restrict__ h0,
    const float*    __restrict__ c0,
    const uint32_t* __restrict__ reset,    // [B,T]
    const uint32_t* __restrict__ clearm,   // [B,T]
    const float*    __restrict__ nstd,     // [B,T]
    const float*    __restrict__ noise,    // [T,B,H]
    const float*    __restrict__ w_hh,     // [2048,512]
    float*          __restrict__ out)
{
    extern __shared__ __align__(16) unsigned char sm[];
    __half* W_s = (__half*)sm;                       // 196608 B (init only)
    __half* A_s = (__half*)(sm + 196608);            // 16 x 520 halves

    const int tid  = threadIdx.x;
    const int cb   = blockIdx.x;
    const int mg   = cb >> 4, cg = cb & 15;
    const int b0   = mg * 16, j0 = cg * 32;
    const int lane = tid & 31, w = tid >> 5;
    const unsigned FM = 0xFFFFFFFFu;

    // ---- W_s fill (once), GATE-INTERLEAVED col order (R12)
    for (int e = tid; e < 4096; e += 256) {
        int ks = e >> 7, c = e & 127;
        int wp = c >> 4, idx = c & 15;
        int ti = idx >> 3, p = idx & 7;
        int n  = (ti * 2 + (p & 1)) * 512 + j0 + wp * 4 + (p >> 1);
        const float4* wpn = reinterpret_cast<const float4*>(&w_hh[(size_t)n * 512 + ks * 16]);
        float4 w0 = wpn[0], w1 = wpn[1], w2 = wpn[2], w3 = wpn[3];
        uint4 lo, hi;
        lo.x = h2u(w0.x, w0.y); lo.y = h2u(w0.z, w0.w);
        lo.z = h2u(w1.x, w1.y); lo.w = h2u(w1.z, w1.w);
        hi.x = h2u(w2.x, w2.y); hi.y = h2u(w2.z, w2.w);
        hi.z = h2u(w3.x, w3.y); hi.w = h2u(w3.z, w3.w);
        char* base = (char*)W_s + (size_t)(ks * 128 + c) * 48;
        *reinterpret_cast<uint4*>(base)      = lo;
        *reinterpret_cast<uint4*>(base + 16) = hi;
    }
    __syncthreads();

    const uint32_t smBase = (uint32_t)__cvta_generic_to_shared(sm);
    const uint32_t As_sa  = smBase + 196608;
    const int mq = lane >> 3, rl = lane & 7;
    const int rowL = (mq & 1) * 8 + rl;
    const int koff = (mq >> 1) * 8;
    const uint32_t aAddr0 = As_sa + rowL * 1040 + koff * 2;
    const uint32_t bAddr0 = smBase + (w * 16 + rowL) * 48 + koff * 2;
    uint32_t bb[32][4];
    #pragma unroll
    for (int ks = 0; ks < 32; ++ks)
        ldsm4(bb[ks], bAddr0 + ks * 6144);

    const int rE = lane >> 2, jE = lane & 3;
    const int bA = b0 + rE, bB = bA + 8;
    const int j  = j0 + w * 4 + jE;

    float cst0, cst1;
    {
        float hA = h0[bA * H_ + j], cA = c0[bA * H_ + j];
        float hB = h0[bB * H_ + j], cB = c0[bB * H_ + j];
        bool mA = ((reset[bA * T_] | clearm[bA * T_]) != 0u);
        bool mB = ((reset[bB * T_] | clearm[bB * T_]) != 0u);
        if (mA) { hA = cA = 0.f; }
        if (mB) { hB = cB = 0.f; }
        float nzA = noise[(size_t)bA * H_ + j] * nstd[bA * T_];
        float nzB = noise[(size_t)bB * H_ + j] * nstd[bB * T_];
        hA += nzA; cA += nzA;
        hB += nzB; cB += nzB;
        g_h2[0][bA * H_ + j] = __float2half_rn(hA);
        g_h2[0][bB * H_ + j] = __float2half_rn(hB);
        cst0 = cA; cst1 = cB;
    }
    __syncthreads();
    if (tid == 0)
        asm volatile("st.release.gpu.global.u32 [%0], %1;"
                     :: "l"(&g_flag[mg][0][cg]), "r"(1u) : "memory");

    // staging map (per chunk): 2 x 16B per thread; idx covers 16 rows x 32 octets
    // chunk ch covers k cols [ch*256, ch*256+256)
    const int sR0 = tid >> 5;            // rows: sR0 and sR0+8
    const int sC0 = tid & 31;            // octet within chunk

    for (int t = 0; t < T_; ++t) {
        // ---- prefetch (independent of h[t]) ----
        size_t xbA = ((size_t)t * B_ + bA) * G4 + j;
        size_t xbB = ((size_t)t * B_ + bB) * G4 + j;
        float xI0 = __half2float(g_Xg[xbA]),        xI1 = __half2float(g_Xg[xbB]);
        float xF0 = __half2float(g_Xg[xbA + 512]),  xF1 = __half2float(g_Xg[xbB + 512]);
        float xG0 = __half2float(g_Xg[xbA + 1024]), xG1 = __half2float(g_Xg[xbB + 1024]);
        float xO0 = __half2float(g_Xg[xbA + 1536]), xO1 = __half2float(g_Xg[xbB + 1536]);
        unsigned mN0 = 0, mN1 = 0;
        float sN0 = 0.f, sN1 = 0.f, nz0 = 0.f, nz1 = 0.f;
        if (t + 1 < T_) {
            mN0 = reset[bA * T_ + t + 1] | clearm[bA * T_ + t + 1];
            mN1 = reset[bB * T_ + t + 1] | clearm[bB * T_ + t + 1];
            sN0 = nstd[bA * T_ + t + 1];
            sN1 = nstd[bB * T_ + t + 1];
            nz0 = noise[((size_t)(t + 1) * B_ + bA) * H_ + j];
            nz1 = noise[((size_t)(t + 1) * B_ + bB) * H_ + j];
        }

        // ---- parallel flag poll (all warps; lane<16 each watch one rank) ----
        {
            const unsigned* fp = &g_flag[mg][t][lane & 15];
            unsigned v = 1;
            const bool mine = lane < NG;
            #pragma unroll 1
            do {
                if (mine)
                    asm volatile("ld.acquire.gpu.global.u32 %0, [%1];"
                                 : "=r"(v) : "l"(fp) : "memory");
            } while (!__all_sync(FM, v != 0));
        }
        // rolling reset of stale flags (safe: all peers passed wait[t-1])
        if (cg == 0 && w == 0 && t >= 1 && lane < NG)
            g_flag[mg][t - 1][lane] = 0;

        // ---- stage h tile in TWO k-chunks (8KB each, separate groups) ----
        const __half* __restrict__ hsrc = g_h2[t & 1];
        #pragma unroll
        for (int ch = 0; ch < 2; ch++) {
            #pragma unroll
            for (int i = 0; i < 2; i++) {
                int r = sR0 + i * 8;
                cp16(As_sa + r * 1040 + ch * 512 + sC0 * 16,
                     &hsrc[(b0 + r) * H_ + ch * 256 + sC0 * 8]);
            }
            asm volatile("cp.async.commit_group;");
        }

        // ---- GEMM half 0 (chunk 0 landed; chunk 1 still in flight) ----
        float a0A[4] = {0.f, 0.f, 0.f, 0.f}, a1A[4] = {0.f, 0.f, 0.f, 0.f};
        float a0B[4] = {0.f, 0.f, 0.f, 0.f}, a1B[4] = {0.f, 0.f, 0.f, 0.f};
        asm volatile("cp.async.wait_group 1;" ::: "memory");
        __syncthreads();
        #pragma unroll
        for (int ks = 0; ks < 16; ks += 2) {
            uint32_t a[4], a2[4];
            ldsm4(a,  aAddr0 + ks * 32);
            ldsm4(a2, aAddr0 + ks * 32 + 32);
            mma_f16(a0A, a,  bb[ks][0],     bb[ks][2]);
            mma_f16(a1A, a,  bb[ks][1],     bb[ks][3]);
            mma_f16(a0B, a2, bb[ks + 1][0], bb[ks + 1][2]);
            mma_f16(a1B, a2, bb[ks + 1][1], bb[ks + 1][3]);
        }
        // ---- GEMM half 1 ----
        asm volatile("cp.async.wait_group 0;" ::: "memory");
        __syncthreads();
        #pragma unroll
        for (int ks = 16; ks < 32; ks += 2) {
            uint32_t a[4], a2[4];
            ldsm4(a,  aAddr0 + ks * 32);
            ldsm4(a2, aAddr0 + ks * 32 + 32);
            mma_f16(a0A, a,  bb[ks][0],     bb[ks][2]);
            mma_f16(a1A, a,  bb[ks][1],     bb[ks][3]);
            mma_f16(a0B, a2, bb[ks + 1][0], bb[ks + 1][2]);
            mma_f16(a1B, a2, bb[ks + 1][1], bb[ks + 1][3]);
        }

        // acc0 = {i(r,j), f(r,j), i(r+8,j), f(r+8,j)}; acc1 = {g, o, g, o}
        float gi0 = a0A[0] + a0B[0], gf0 = a0A[1] + a0B[1];
        float gi1 = a0A[2] + a0B[2], gf1 = a0A[3] + a0B[3];
        float gg0 = a1A[0] + a1B[0], go0 = a1A[1] + a1B[1];
        float gg1 = a1A[2] + a1B[2], go1 = a1A[3] + a1B[3];

        // ---- gates + state update + next-step preprocessing ----
        float iA = sigf(gi0 + xI0),     iB = sigf(gi1 + xI1);
        float fA = sigf(gf0 + xF0),     fB = sigf(gf1 + xF1);
        float gA = tanhfast(gg0 + xG0), gB = tanhfast(gg1 + xG1);
        float oA = sigf(go0 + xO0),     oB = sigf(go1 + xO1);

        float cnA = fA * cst0 + iA * gA;
        float cnB = fB * cst1 + iB * gB;
        float hnA = oA * tanhfast(cnA);
        float hnB = oB * tanhfast(cnB);

        if (t + 1 < T_) {
            float hwA = mN0 ? 0.f : hnA, cwA = mN0 ? 0.f : cnA;
            float hwB = mN1 ? 0.f : hnB, cwB = mN1 ? 0.f : cnB;
            hwA += nz0 * sN0; cwA += nz0 * sN0;
            hwB += nz1 * sN1; cwB += nz1 * sN1;
            g_h2[(t + 1) & 1][bA * H_ + j] = __float2half_rn(hwA);
            g_h2[(t + 1) & 1][bB * H_ + j] = __float2half_rn(hwB);
            cst0 = cwA; cst1 = cwB;
        }

        __syncthreads();
        if (tid == 0)
            asm volatile("st.release.gpu.global.u32 [%0], %1;"
                         :: "l"(&g_flag[mg][t + 1][cg]), "r"(1u) : "memory");

        // ---- off-critical-path output stores ----
        out[((size_t)t * B_ + bA) * H_ + j] = hnA;
        out[((size_t)t * B_ + bB) * H_ + j] = hnB;
        if (t == T_ - 1) {
            out[(size_t)T_ * (B_ * H_)           + bA * H_ + j] = hnA;
            out[(size_t)T_ * (B_ * H_)           + bB * H_ + j] = hnB;
            out[(size_t)T_ * (B_ * H_) + B_ * H_ + bA * H_ + j] = cnA;
            out[(size_t)T_ * (B_ * H_) + B_ * H_ + bB * H_ + j] = cnB;
        }
    }

    // ---- end sync + restore flags to zero for graph replays ----
    if (cg == 0 && w == 0) {
        const unsigned* fp = &g_flag[mg][T_][lane & 15];
        unsigned v = 1;
        const bool mine = lane < NG;
        #pragma unroll 1
        do {
            if (mine)
                asm volatile("ld.acquire.gpu.global.u32 %0, [%1];"
                             : "=r"(v) : "l"(fp) : "memory");
        } while (!__all_sync(FM, v != 0));
        if (lane < NG) {
            g_flag[mg][T_ - 1][lane] = 0;
            g_flag[mg][T_][lane]     = 0;
        }
    }
}

// ==========================================================================
extern "C" void kernel_launch(void* const* d_in, const int* in_sizes, int n_in,
                              void* d_out, int out_size) {
    (void)in_sizes; (void)n_in; (void)out_size;
    const float*    latent = (const float*)d_in[0];
    const float*    h0     = (const float*)d_in[1];
    const float*    c0     = (const float*)d_in[2];
    const uint32_t* reset  = (const uint32_t*)d_in[3];
    const uint32_t* clearm = (const uint32_t*)d_in[4];
    const float*    nstd   = (const float*)d_in[5];
    const float*    noise  = (const float*)d_in[6];
    const float*    w_ih   = (const float*)d_in[7];
    const float*    w_hh   = (const float*)d_in[8];
    const float*    b_ih   = (const float*)d_in[9];
    const float*    b_hh   = (const float*)d_in[10];
    float* out = (float*)d_out;

    const int smem1 = 512 + 4 * 18432;                 // 74240 B
    const int smem2 = 196608 + 16640;                  // 213248 B
    cudaFuncSetAttribute(xgemm_fp16, cudaFuncAttributeMaxDynamicSharedMemorySize, smem1);
    cudaFuncSetAttribute(lstm_rec16, cudaFuncAttributeMaxDynamicSharedMemorySize, smem2);

    conv_lat<<<4096, 256>>>(latent);
    conv_w<<<512, 256>>>(w_ih);
    xgemm_fp16<<<512 * 16, 256, smem1>>>(b_ih, b_hh);
    lstm_rec16<<<128, 256, smem2>>>(h0, c0, reset, clearm, nstd, noise, w_hh, out);
}

// round 17
// speedup vs baseline: 1.5982x; 1.0001x over previous
#include <cuda_runtime.h>
#include <cuda_fp16.h>
#include <cstdint>
#include <cstddef>

#define T_   512
#define B_   128
#define H_   512
#define G4   2048
#define NG   16      // CTAs per row-group (phase 2)

// ---------------- scratch (device globals; no allocation) ----------------
__device__ __half   g_Xg[(size_t)T_ * B_ * G4];     // 256 MB fp16: x@W_ih^T + bias
__device__ __half   g_lat16[(size_t)T_ * B_ * 512]; // 64 MB, tiled [tt][kt][r][32]
__device__ uint32_t g_w16p[16 * 16 * 2 * 128 * 8];  // 2 MB, smem-layout-ready
__device__ __align__(16) unsigned char g_hf[2][8][16384]; // h in mma A-frag layout
__device__ unsigned g_flag[8][T_ + 1][NG];          // per-group per-step flags

// ---------------- helpers ----------------
__device__ __forceinline__ void mma_f16(float c[4], const uint32_t a[4],
                                        uint32_t b0, uint32_t b1) {
    asm volatile(
        "mma.sync.aligned.m16n8k16.row.col.f32.f16.f16.f32 "
        "{%0,%1,%2,%3},{%4,%5,%6,%7},{%8,%9},{%0,%1,%2,%3};"
        : "+f"(c[0]), "+f"(c[1]), "+f"(c[2]), "+f"(c[3])
        : "r"(a[0]), "r"(a[1]), "r"(a[2]), "r"(a[3]), "r"(b0), "r"(b1));
}
__device__ __forceinline__ void ldsm4(uint32_t r[4], uint32_t saddr) {
    asm volatile("ldmatrix.sync.aligned.m8n8.x4.shared.b16 {%0,%1,%2,%3},[%4];"
        : "=r"(r[0]), "=r"(r[1]), "=r"(r[2]), "=r"(r[3]) : "r"(saddr));
}
__device__ __forceinline__ void cp16(uint32_t sdst, const void* gsrc) {
    asm volatile("cp.async.ca.shared.global [%0],[%1],16;" :: "r"(sdst), "l"(gsrc));
}
__device__ __forceinline__ uint32_t h2u(float x, float y) {
    __half2 h = __floats2half2_rn(x, y);
    return *reinterpret_cast<uint32_t*>(&h);
}
__device__ __forceinline__ float sigf(float x) {
    return __fdividef(1.0f, 1.0f + __expf(-x));
}
__device__ __forceinline__ float tanhfast(float x) {
    return 1.0f - 2.0f * __fdividef(1.0f, __expf(2.0f * x) + 1.0f);
}

// ==========================================================================
// Convert latent -> fp16, tiled layout [(tt*16+kt)*128 + r][32]   (R12)
// ==========================================================================
__global__ void __launch_bounds__(256) conv_lat(const float* __restrict__ latent) {
    const size_t n = (size_t)T_ * B_ * 512 / 2;   // half2 units
    uint32_t* dst = reinterpret_cast<uint32_t*>(g_lat16);
    for (size_t i = (size_t)blockIdx.x * 256 + threadIdx.x; i < n;
         i += (size_t)gridDim.x * 256) {
        size_t hidx = i * 2;
        int    k    = (int)(hidx & 31);
        size_t rest = hidx >> 5;
        int    r    = (int)(rest & 127);
        size_t r2   = rest >> 7;
        int    kt   = (int)(r2 & 15);
        size_t tt   = r2 >> 4;
        size_t src  = (tt * 128 + r) * 512 + kt * 32 + k;
        float2 v = *reinterpret_cast<const float2*>(&latent[src]);
        dst[i] = h2u(v.x, v.y);
    }
}

// ==========================================================================
// Convert w_ih -> fp16 permuted smem layout (R12)
// ==========================================================================
__global__ void __launch_bounds__(256) conv_w(const float* __restrict__ w_ih) {
    const int total = 16 * 16 * 2 * 128 * 8;
    for (int d = blockIdx.x * 256 + threadIdx.x; d < total; d += gridDim.x * 256) {
        int q  = d & 7, r = (d >> 3) & 127, ks = (d >> 10) & 1;
        int kt = (d >> 11) & 15, nt = d >> 15;
        int p  = (q & 1) ? (4 + (q >> 1)) : (q >> 1);
        int k  = kt * 32 + ks * 16 + p * 2;
        int n  = nt * 128 + r;
        float2 v = *reinterpret_cast<const float2*>(&w_ih[(size_t)n * 512 + k]);
        g_w16p[d] = h2u(v.x, v.y);
    }
}

// ==========================================================================
// Phase 1: Xg = latent @ W_ih^T + bias -> fp16. 4-stage cp.async ring (R12).
// ==========================================================================
__global__ void __launch_bounds__(256, 2) xgemm_fp16(
    const float* __restrict__ b_ih, const float* __restrict__ b_hh)
{
    extern __shared__ __align__(16) unsigned char sm[];
    float* bias_s = (float*)sm;

    const int tid  = threadIdx.x;
    const int nt   = blockIdx.x & 15;
    const int tt   = blockIdx.x >> 4;
    const int n0   = nt * 128;
    const int lane = tid & 31, w = tid >> 5;
    const int mb   = (w & 3) * 32;
    const int nb2  = (w >> 2) * 64;

    if (tid < 128) bias_s[tid] = b_ih[n0 + tid] + b_hh[n0 + tid];

    const uint32_t smBase = (uint32_t)__cvta_generic_to_shared(sm);

    float c[2][8][4];
    #pragma unroll
    for (int i = 0; i < 2; i++)
        #pragma unroll
        for (int jx = 0; jx < 8; jx++)
            #pragma unroll
            for (int k = 0; k < 4; k++) c[i][jx][k] = 0.f;

    auto ISSUE = [&](int kt, int s) {
        uint32_t Aa = smBase + 512 + s * 18432;
        uint32_t Ba = Aa + 10240;
        const __half* asrc = g_lat16 + ((size_t)(tt * 16 + kt) << 12);
        #pragma unroll
        for (int i = 0; i < 2; i++) {
            int cch = tid + i * 256;
            int r = cch >> 2, c4 = cch & 3;
            cp16(Aa + r * 80 + c4 * 16, asrc + r * 32 + c4 * 8);
        }
        const uint32_t* wsrc = g_w16p + (size_t)(nt * 16 + kt) * 2048;
        #pragma unroll
        for (int i = 0; i < 2; i++) {
            int cch = tid + i * 256;
            cp16(Ba + cch * 16, wsrc + cch * 4);
        }
        asm volatile("cp.async.commit_group;");
    };

    auto COMPUTE = [&](int s) {
        const uint32_t* Au = (const uint32_t*)(sm + 512 + s * 18432);
        const uint32_t* Bs = (const uint32_t*)(sm + 512 + s * 18432 + 10240);
        #pragma unroll
        for (int ks = 0; ks < 2; ++ks) {
            uint32_t a[2][4];
            #pragma unroll
            for (int mi = 0; mi < 2; mi++) {
                int base = (mb + mi * 16 + (lane >> 2)) * 20 + ks * 8 + (lane & 3);
                a[mi][0] = Au[base];       a[mi][1] = Au[base + 160];
                a[mi][2] = Au[base + 4];   a[mi][3] = Au[base + 164];
            }
            #pragma unroll
            for (int ni = 0; ni < 8; ++ni) {
                int n = nb2 + ni * 8 + (lane >> 2);
                uint2 bv = *reinterpret_cast<const uint2*>(&Bs[(ks * 128 + n) * 8 + (lane & 3) * 2]);
                mma_f16(c[0][ni], a[0], bv.x, bv.y);
                mma_f16(c[1][ni], a[1], bv.x, bv.y);
            }
        }
    };

    ISSUE(0, 0); ISSUE(1, 1); ISSUE(2, 2);
    #pragma unroll 1
    for (int kt = 0; kt < 16; ++kt) {
        if (kt <= 13)      asm volatile("cp.async.wait_group 2;");
        else if (kt == 14) asm volatile("cp.async.wait_group 1;");
        else               asm volatile("cp.async.wait_group 0;");
        __syncthreads();
        COMPUTE(kt & 3);
        if (kt + 3 < 16) ISSUE(kt + 3, (kt + 3) & 3);
    }

    #pragma unroll
    for (int mi = 0; mi < 2; mi++) {
        #pragma unroll
        for (int ni = 0; ni < 8; ni++) {
            int r    = mb + mi * 16 + (lane >> 2);
            int colL = nb2 + ni * 8 + (lane & 3) * 2;
            float bv0 = bias_s[colL], bv1 = bias_s[colL + 1];
            size_t base = ((size_t)(tt * 128 + r)) * G4 + n0 + colL;
            *reinterpret_cast<uint32_t*>(&g_Xg[base]) =
                h2u(c[mi][ni][0] + bv0, c[mi][ni][1] + bv1);
            *reinterpret_cast<uint32_t*>(&g_Xg[base + (size_t)8 * G4]) =
                h2u(c[mi][ni][2] + bv0, c[mi][ni][3] + bv1);
        }
    }
}

// ==========================================================================
// Phase 2: persistent recurrence — R12/R16 structure, but h exchanged in
// mma A-FRAGMENT global layout (g_hf): producers scatter-store their slice,
// consumers LDG.128 fragments directly into mma (no smem staging, no LDSM
// for A, no staging syncs). Flags/poll, gate-interleaved W, reg-resident W
// fragments, epilogue all unchanged.
// g_hf line (ks,l) 16B = {A[r][kc,kc+1] | A[r+8][kc,kc+1] | A[r][kc+8,+9] |
// A[r+8][kc+8,+9]}, r=l>>2, kc=ks*16+(l&3)*2  (validated in R11).
// ==========================================================================
__global__ void __launch_bounds__(256, 1) lstm_rec16(
    const float*    __restrict__ h0,
    const float*    __restrict__ c0,
    const uint32_t* __restrict__ reset,    // [B,T]
    const uint32_t* __restrict__ clearm,   // [B,T]
    const float*    __restrict__ nstd,     // [B,T]
    const float*    __restrict__ noise,    // [T,B,H]
    const float*    __restrict__ w_hh,     // [2048,512]
    float*          __restrict__ out)
{
    extern __shared__ __align__(16) unsigned char sm[];
    __half* W_s = (__half*)sm;                       // 196608 B (init only)

    const int tid  = threadIdx.x;
    const int cb   = blockIdx.x;
    const int mg   = cb >> 4, cg = cb & 15;
    const int b0   = mg * 16, j0 = cg * 32;
    const int lane = tid & 31, w = tid >> 5;
    const unsigned FM = 0xFFFFFFFFu;

    // ---- W_s fill (once), GATE-INTERLEAVED col order (R12)
    for (int e = tid; e < 4096; e += 256) {
        int ks = e >> 7, c = e & 127;
        int wp = c >> 4, idx = c & 15;
        int ti = idx >> 3, p = idx & 7;
        int n  = (ti * 2 + (p & 1)) * 512 + j0 + wp * 4 + (p >> 1);
        const float4* wpn = reinterpret_cast<const float4*>(&w_hh[(size_t)n * 512 + ks * 16]);
        float4 w0 = wpn[0], w1 = wpn[1], w2 = wpn[2], w3 = wpn[3];
        uint4 lo, hi;
        lo.x = h2u(w0.x, w0.y); lo.y = h2u(w0.z, w0.w);
        lo.z = h2u(w1.x, w1.y); lo.w = h2u(w1.z, w1.w);
        hi.x = h2u(w2.x, w2.y); hi.y = h2u(w2.z, w2.w);
        hi.z = h2u(w3.x, w3.y); hi.w = h2u(w3.z, w3.w);
        char* base = (char*)W_s + (size_t)(ks * 128 + c) * 48;
        *reinterpret_cast<uint4*>(base)      = lo;
        *reinterpret_cast<uint4*>(base + 16) = hi;
    }
    __syncthreads();

    // ---- load all W fragments into registers
    const uint32_t smBase = (uint32_t)__cvta_generic_to_shared(sm);
    const int mq = lane >> 3, rl = lane & 7;
    const int rowL = (mq & 1) * 8 + rl;
    const int koff = (mq >> 1) * 8;
    const uint32_t bAddr0 = smBase + (w * 16 + rowL) * 48 + koff * 2;
    uint32_t bb[32][4];
    #pragma unroll
    for (int ks = 0; ks < 32; ++ks)
        ldsm4(bb[ks], bAddr0 + ks * 6144);

    // ---- epilogue lane mapping (R12: gates land in-lane)
    const int rE = lane >> 2, jE = lane & 3;
    const int bA = b0 + rE, bB = bA + 8;
    const int j  = j0 + w * 4 + jE;

    // ---- producer fragment-scatter offset (within a group's 16 KB buffer)
    const int jl   = w * 4 + jE;                 // local col 0..31
    const int ksP  = cg * 2 + (jl >> 4);         // global kstep this col feeds
    const int jj   = jl & 15;
    const int lfP  = rE * 4 + ((jj & 7) >> 1);
    const int offP = ((jj >= 8) ? 8 : 0) + (jj & 1) * 2;
    const size_t pOff = (size_t)(ksP * 32 + lfP) * 16 + offP;   // hwA; hwB at +4

    // ---- init h/c with step-0 preprocessing; publish fragments
    float cst0, cst1;
    {
        float hA = h0[bA * H_ + j], cA = c0[bA * H_ + j];
        float hB = h0[bB * H_ + j], cB = c0[bB * H_ + j];
        bool mA = ((reset[bA * T_] | clearm[bA * T_]) != 0u);
        bool mB = ((reset[bB * T_] | clearm[bB * T_]) != 0u);
        if (mA) { hA = cA = 0.f; }
        if (mB) { hB = cB = 0.f; }
        float nzA = noise[(size_t)bA * H_ + j] * nstd[bA * T_];
        float nzB = noise[(size_t)bB * H_ + j] * nstd[bB * T_];
        hA += nzA; cA += nzA;
        hB += nzB; cB += nzB;
        unsigned char* hp = &g_hf[0][mg][0];
        *(__half*)(hp + pOff)     = __float2half_rn(hA);
        *(__half*)(hp + pOff + 4) = __float2half_rn(hB);
        cst0 = cA; cst1 = cB;
    }
    __syncthreads();
    if (tid == 0)
        asm volatile("st.release.gpu.global.u32 [%0], %1;"
                     :: "l"(&g_flag[mg][0][cg]), "r"(1u) : "memory");

    for (int t = 0; t < T_; ++t) {
        // ---- prefetch (independent of h[t]) ----
        size_t xbA = ((size_t)t * B_ + bA) * G4 + j;
        size_t xbB = ((size_t)t * B_ + bB) * G4 + j;
        float xI0 = __half2float(g_Xg[xbA]),        xI1 = __half2float(g_Xg[xbB]);
        float xF0 = __half2float(g_Xg[xbA + 512]),  xF1 = __half2float(g_Xg[xbB + 512]);
        float xG0 = __half2float(g_Xg[xbA + 1024]), xG1 = __half2float(g_Xg[xbB + 1024]);
        float xO0 = __half2float(g_Xg[xbA + 1536]), xO1 = __half2float(g_Xg[xbB + 1536]);
        unsigned mN0 = 0, mN1 = 0;
        float sN0 = 0.f, sN1 = 0.f, nz0 = 0.f, nz1 = 0.f;
        if (t + 1 < T_) {
            mN0 = reset[bA * T_ + t + 1] | clearm[bA * T_ + t + 1];
            mN1 = reset[bB * T_ + t + 1] | clearm[bB * T_ + t + 1];
            sN0 = nstd[bA * T_ + t + 1];
            sN1 = nstd[bB * T_ + t + 1];
            nz0 = noise[((size_t)(t + 1) * B_ + bA) * H_ + j];
            nz1 = noise[((size_t)(t + 1) * B_ + bB) * H_ + j];
        }

        // ---- parallel flag poll (all warps; lane<16 each watch one rank) ----
        {
            const unsigned* fp = &g_flag[mg][t][lane & 15];
            unsigned v = 1;
            const bool mine = lane < NG;
            #pragma unroll 1
            do {
                if (mine)
                    asm volatile("ld.acquire.gpu.global.u32 %0, [%1];"
                                 : "=r"(v) : "l"(fp) : "memory");
            } while (!__all_sync(FM, v != 0));
        }
        // rolling reset of stale flags (safe: all peers passed wait[t-1])
        if (cg == 0 && w == 0 && t >= 1 && lane < NG)
            g_flag[mg][t - 1][lane] = 0;

        // ---- GEMM: 32 ksteps; A fragments via direct LDG.128, 8-deep pipe ----
        const unsigned char* __restrict__ Ab = &g_hf[t & 1][mg][0];
        uint4 af[8];
        #pragma unroll
        for (int i = 0; i < 8; i++)
            af[i] = *reinterpret_cast<const uint4*>(Ab + (size_t)(i * 32 + lane) * 16);

        float a0A[4] = {0.f, 0.f, 0.f, 0.f}, a1A[4] = {0.f, 0.f, 0.f, 0.f};
        float a0B[4] = {0.f, 0.f, 0.f, 0.f}, a1B[4] = {0.f, 0.f, 0.f, 0.f};
        #pragma unroll
        for (int ks = 0; ks < 32; ++ks) {
            uint32_t a[4] = {af[ks & 7].x, af[ks & 7].y, af[ks & 7].z, af[ks & 7].w};
            if (ks + 8 < 32)
                af[ks & 7] = *reinterpret_cast<const uint4*>(
                    Ab + (size_t)((ks + 8) * 32 + lane) * 16);
            if (ks & 1) {
                mma_f16(a0B, a, bb[ks][0], bb[ks][2]);
                mma_f16(a1B, a, bb[ks][1], bb[ks][3]);
            } else {
                mma_f16(a0A, a, bb[ks][0], bb[ks][2]);
                mma_f16(a1A, a, bb[ks][1], bb[ks][3]);
            }
        }
        // acc0 = {i(r,j), f(r,j), i(r+8,j), f(r+8,j)}; acc1 = {g, o, g, o}
        float gi0 = a0A[0] + a0B[0], gf0 = a0A[1] + a0B[1];
        float gi1 = a0A[2] + a0B[2], gf1 = a0A[3] + a0B[3];
        float gg0 = a1A[0] + a1B[0], go0 = a1A[1] + a1B[1];
        float gg1 = a1A[2] + a1B[2], go1 = a1A[3] + a1B[3];

        // ---- gates + state update + next-step preprocessing ----
        float iA = sigf(gi0 + xI0),     iB = sigf(gi1 + xI1);
        float fA = sigf(gf0 + xF0),     fB = sigf(gf1 + xF1);
        float gA = tanhfast(gg0 + xG0), gB = tanhfast(gg1 + xG1);
        float oA = sigf(go0 + xO0),     oB = sigf(go1 + xO1);

        float cnA = fA * cst0 + iA * gA;
        float cnB = fB * cst1 + iB * gB;
        float hnA = oA * tanhfast(cnA);
        float hnB = oB * tanhfast(cnB);

        if (t + 1 < T_) {
            float hwA = mN0 ? 0.f : hnA, cwA = mN0 ? 0.f : cnA;
            float hwB = mN1 ? 0.f : hnB, cwB = mN1 ? 0.f : cnB;
            hwA += nz0 * sN0; cwA += nz0 * sN0;
            hwB += nz1 * sN1; cwB += nz1 * sN1;
            unsigned char* hp = &g_hf[(t + 1) & 1][mg][0];
            *(__half*)(hp + pOff)     = __float2half_rn(hwA);
            *(__half*)(hp + pOff + 4) = __float2half_rn(hwB);
            cst0 = cwA; cst1 = cwB;
        }

        __syncthreads();
        if (tid == 0)
            asm volatile("st.release.gpu.global.u32 [%0], %1;"
                         :: "l"(&g_flag[mg][t + 1][cg]), "r"(1u) : "memory");

        // ---- off-critical-path output stores ----
        out[((size_t)t * B_ + bA) * H_ + j] = hnA;
        out[((size_t)t * B_ + bB) * H_ + j] = hnB;
        if (t == T_ - 1) {
            out[(size_t)T_ * (B_ * H_)           + bA * H_ + j] = hnA;
            out[(size_t)T_ * (B_ * H_)           + bB * H_ + j] = hnB;
            out[(size_t)T_ * (B_ * H_) + B_ * H_ + bA * H_ + j] = cnA;
            out[(size_t)T_ * (B_ * H_) + B_ * H_ + bB * H_ + j] = cnB;
        }
    }

    // ---- end sync + restore flags to zero for graph replays ----
    if (cg == 0 && w == 0) {
        const unsigned* fp = &g_flag[mg][T_][lane & 15];
        unsigned v = 1;
        const bool mine = lane < NG;
        #pragma unroll 1
        do {
            if (mine)
                asm volatile("ld.acquire.gpu.global.u32 %0, [%1];"
                             : "=r"(v) : "l"(fp) : "memory");
        } while (!__all_sync(FM, v != 0));
        if (lane < NG) {
            g_flag[mg][T_ - 1][lane] = 0;
            g_flag[mg][T_][lane]     = 0;
        }
    }
}

// ==========================================================================
extern "C" void kernel_launch(void* const* d_in, const int* in_sizes, int n_in,
                              void* d_out, int out_size) {
    (void)in_sizes; (void)n_in; (void)out_size;
    const float*    latent = (const float*)d_in[0];
    const float*    h0     = (const float*)d_in[1];
    const float*    c0     = (const float*)d_in[2];
    const uint32_t* reset  = (const uint32_t*)d_in[3];
    const uint32_t* clearm = (const uint32_t*)d_in[4];
    const float*    nstd   = (const float*)d_in[5];
    const float*    noise  = (const float*)d_in[6];
    const float*    w_ih   = (const float*)d_in[7];
    const float*    w_hh   = (const float*)d_in[8];
    const float*    b_ih   = (const float*)d_in[9];
    const float*    b_hh   = (const float*)d_in[10];
    float* out = (float*)d_out;

    const int smem1 = 512 + 4 * 18432;                 // 74240 B
    const int smem2 = 196608;                          // W init region only
    cudaFuncSetAttribute(xgemm_fp16, cudaFuncAttributeMaxDynamicSharedMemorySize, smem1);
    cudaFuncSetAttribute(lstm_rec16, cudaFuncAttributeMaxDynamicSharedMemorySize, smem2);

    conv_lat<<<4096, 256>>>(latent);
    conv_w<<<512, 256>>>(w_ih);
    xgemm_fp16<<<512 * 16, 256, smem1>>>(b_ih, b_hh);
    lstm_rec16<<<128, 256, smem2>>>(h0, c0, reset, clearm, nstd, noise, w_hh, out);
}